// round 13
// baseline (speedup 1.0000x reference)
#include <cuda_runtime.h>
#include <cuda_fp16.h>
#include <math.h>
#include <stdint.h>

#define SEQ 2048
#define DMODEL 1024
#define NH 16
#define HDK 64

// ---------------------------------------------------------------------------
// Scratch (__device__ globals).
// ---------------------------------------------------------------------------
__device__ __half g_Xhi[3][SEQ * DMODEL];    // inputs Q,K,V (hi)
__device__ __half g_Xlo[3][SEQ * DMODEL];    // inputs lo (used by V-proj only)
__device__ __half g_Wh[4][DMODEL * DMODEL];  // Wq,Wk,Wv,Wo as [N][K], single fp16
__device__ __half g_P[3][SEQ * DMODEL];      // projected q,k,v (q pre-scaled), fp16
__device__ __half g_Ohi[SEQ * DMODEL];       // concat hi
__device__ __half g_Olo[SEQ * DMODEL];       // concat lo

#define ONESH2 0x3C003C00u   // {1.0h, 1.0h}

// ---------------------------------------------------------------------------
// Helpers
// ---------------------------------------------------------------------------
__device__ __forceinline__ uint32_t smem_u32(const void* p) {
    uint32_t a;
    asm("{ .reg .u64 t; cvta.to.shared.u64 t, %1; cvt.u32.u64 %0, t; }" : "=r"(a) : "l"(p));
    return a;
}

#define CP16(dst, src) \
    asm volatile("cp.async.cg.shared.global [%0], [%1], 16;" :: "r"((uint32_t)(dst)), "l"(src) : "memory")
#define CP_COMMIT() asm volatile("cp.async.commit_group;" ::: "memory")
#define CP_WAIT0()  asm volatile("cp.async.wait_group 0;" ::: "memory")
#define CP_WAIT1()  asm volatile("cp.async.wait_group 1;" ::: "memory")

__device__ __forceinline__ void ldsm4(uint32_t* r, uint32_t addr) {
    asm volatile("ldmatrix.sync.aligned.m8n8.x4.shared.b16 {%0,%1,%2,%3}, [%4];"
                 : "=r"(r[0]), "=r"(r[1]), "=r"(r[2]), "=r"(r[3]) : "r"(addr));
}
__device__ __forceinline__ void ldsm4t(uint32_t* r, uint32_t addr) {
    asm volatile("ldmatrix.sync.aligned.m8n8.x4.trans.shared.b16 {%0,%1,%2,%3}, [%4];"
                 : "=r"(r[0]), "=r"(r[1]), "=r"(r[2]), "=r"(r[3]) : "r"(addr));
}
__device__ __forceinline__ void mma16816h(float* c, const uint32_t* a, uint32_t b0, uint32_t b1) {
    asm volatile("mma.sync.aligned.m16n8k16.row.col.f32.f16.f16.f32 "
                 "{%0,%1,%2,%3}, {%4,%5,%6,%7}, {%8,%9}, {%0,%1,%2,%3};"
                 : "+f"(c[0]), "+f"(c[1]), "+f"(c[2]), "+f"(c[3])
                 : "r"(a[0]), "r"(a[1]), "r"(a[2]), "r"(a[3]), "r"(b0), "r"(b1));
}

__device__ __forceinline__ uint32_t h2u(__half2 h) { return *reinterpret_cast<uint32_t*>(&h); }
__device__ __forceinline__ void hilo_packh(float x, float y, uint32_t& ph, uint32_t& pl) {
    __half2 h = __floats2half2_rn(x, y);
    ph = h2u(h);
    float lx = x - __low2float(h);
    float ly = y - __high2float(h);
    pl = h2u(__floats2half2_rn(lx, ly));
}

// ldmatrix address generators, parametric row pitch P (bytes).
__device__ __forceinline__ uint32_t a_addr(uint32_t tb, int r0, int kb, int lane, int P) {
    int sub = lane >> 3, ll = lane & 7;
    return tb + (uint32_t)(r0 + ((sub & 1) << 3) + ll) * P + kb + ((sub >> 1) << 4);
}
__device__ __forceinline__ uint32_t b_addr(uint32_t tb, int n0, int kb, int lane, int P) {
    int sub = lane >> 3, ll = lane & 7;
    return tb + (uint32_t)(n0 + ((sub >> 1) << 3) + ll) * P + kb + ((sub & 1) << 4);
}
__device__ __forceinline__ uint32_t v_addr(uint32_t tb, int k0, int nb, int lane, int P) {
    int sub = lane >> 3, ll = lane & 7;
    return tb + (uint32_t)(k0 + ((sub & 1) << 3) + ll) * P + nb + ((sub >> 1) << 4);
}

// ---------------------------------------------------------------------------
// Conversion kernels
// ---------------------------------------------------------------------------
__global__ void conv_in_kernel(const float* __restrict__ Q, const float* __restrict__ K,
                               const float* __restrict__ V)
{
    int z = blockIdx.y;
    const float* src = (z == 0) ? Q : (z == 1) ? K : V;
    #pragma unroll
    for (int k = 0; k < 2; k++) {
        size_t i = ((size_t)blockIdx.x * 256 + threadIdx.x) * 4 + (size_t)k * (SEQ * DMODEL / 2);
        float4 v = *(const float4*)(src + i);
        uint32_t ph, pl;
        hilo_packh(v.x, v.y, ph, pl);
        *(uint32_t*)&g_Xhi[z][i] = ph; *(uint32_t*)&g_Xlo[z][i] = pl;
        hilo_packh(v.z, v.w, ph, pl);
        *(uint32_t*)&g_Xhi[z][i + 2] = ph; *(uint32_t*)&g_Xlo[z][i + 2] = pl;
    }
}

// Transpose + convert to single fp16: src [R][C] fp32 -> dst [C][R]
__device__ __forceinline__ void conv_w_body(const float* __restrict__ src,
                                            __half* __restrict__ dst,
                                            int R, int C, int bx, int by)
{
    __shared__ float t[64][65];
    int r0 = bx * 64, c0 = by * 64;
    int tid = threadIdx.x;
    #pragma unroll
    for (int i = 0; i < 16; i++) {
        int idx = tid + i * 256;
        int rr = idx >> 6, cc = idx & 63;
        t[cc][rr] = src[(size_t)(r0 + rr) * C + c0 + cc];
    }
    __syncthreads();
    #pragma unroll
    for (int i = 0; i < 16; i++) {
        int idx = tid + i * 256;
        int rr = idx >> 6, cc = idx & 63;
        dst[(size_t)(c0 + rr) * R + r0 + cc] = __float2half_rn(t[rr][cc]);
    }
}

__global__ void conv_w3_kernel(const float* __restrict__ Wq, const float* __restrict__ Wk,
                               const float* __restrict__ Wv)
{
    int which = blockIdx.z >> 4, zz = blockIdx.z & 15;
    const float* src = (which == 0) ? Wq : (which == 1) ? Wk : Wv;
    conv_w_body(src + (size_t)zz * DMODEL * HDK,
                &g_Wh[which][(size_t)zz * DMODEL * HDK], 1024, 64, blockIdx.x, 0);
}

__global__ void conv_wo_kernel(const float* __restrict__ Wo)
{
    conv_w_body(Wo, g_Wh[3], 1024, 1024, blockIdx.x, blockIdx.y);
}

// ---------------------------------------------------------------------------
// HMMA GEMM: C = A[S][1024] * B^T ([N][K]) + bias.
// NT=1: A_hi x B, K-chunk 64 (TPG 144).  NT=2: (A_hi+A_lo) x B, K-chunk 32 (TPG 80).
// CTA 128x128, 8 warps (warp m32xn64), 3-stage cp.async, ONE barrier per chunk.
// ---------------------------------------------------------------------------
// NT1: stage = A(128x144) + B(128x144) = 36864; 3 stages = 110592
// NT2: stage = Ahi + Alo + B (each 128x80=10240) = 30720; 3 stages = 92160
#define G1_TPG 144
#define G1_B   18432
#define G1_STG 36864
#define G2_TPG 80
#define G2_ALO 10240
#define G2_B   20480
#define G2_STG 30720
#define G_SMEM1 (3 * G1_STG)   // 110592
#define G_SMEM2 (3 * G2_STG)   // 92160

template <int NT>
__device__ __forceinline__ void g_load_chunk(
    uint32_t st, const __half* __restrict__ Ahi, const __half* __restrict__ Alo,
    const __half* __restrict__ B, int m0, int n0, int k0, int tid)
{
    if (NT == 1) {
        #pragma unroll
        for (int i = 0; i < 4; i++) {           // A: 128 rows x 8 x 16B
            int j = tid + i * 256;
            int r = j >> 3, c = j & 7;
            CP16(st + (uint32_t)r * G1_TPG + c * 16,
                 Ahi + (size_t)(m0 + r) * DMODEL + k0 + c * 8);
        }
        #pragma unroll
        for (int i = 0; i < 4; i++) {           // B
            int j = tid + i * 256;
            int r = j >> 3, c = j & 7;
            CP16(st + G1_B + (uint32_t)r * G1_TPG + c * 16,
                 B + (size_t)(n0 + r) * DMODEL + k0 + c * 8);
        }
    } else {
        #pragma unroll
        for (int i = 0; i < 2; i++) {
            int j = tid + i * 256;
            int r = j >> 2, c = j & 3;
            CP16(st + (uint32_t)r * G2_TPG + c * 16,
                 Ahi + (size_t)(m0 + r) * DMODEL + k0 + c * 8);
        }
        #pragma unroll
        for (int i = 0; i < 2; i++) {
            int j = tid + i * 256;
            int r = j >> 2, c = j & 3;
            CP16(st + G2_ALO + (uint32_t)r * G2_TPG + c * 16,
                 Alo + (size_t)(m0 + r) * DMODEL + k0 + c * 8);
        }
        #pragma unroll
        for (int i = 0; i < 2; i++) {
            int j = tid + i * 256;
            int r = j >> 2, c = j & 3;
            CP16(st + G2_B + (uint32_t)r * G2_TPG + c * 16,
                 B + (size_t)(n0 + r) * DMODEL + k0 + c * 8);
        }
    }
    CP_COMMIT();
}

template <int NT>
__device__ __forceinline__ void g_compute_chunk(uint32_t st, int lane, int wr, int wc,
                                                float C[2][8][4])
{
    constexpr int TPGx = (NT == 1) ? G1_TPG : G2_TPG;
    constexpr int KS   = (NT == 1) ? 4 : 2;
    constexpr uint32_t BOFF = (NT == 1) ? G1_B : G2_B;
    #pragma unroll
    for (int ks = 0; ks < KS; ks++) {
        int kb = ks * 32;
        uint32_t ah[2][4], al[2][4];
        ldsm4(ah[0], a_addr(st, wr * 32,      kb, lane, TPGx));
        ldsm4(ah[1], a_addr(st, wr * 32 + 16, kb, lane, TPGx));
        if (NT == 2) {
            ldsm4(al[0], a_addr(st + G2_ALO, wr * 32,      kb, lane, TPGx));
            ldsm4(al[1], a_addr(st + G2_ALO, wr * 32 + 16, kb, lane, TPGx));
        }
        #pragma unroll
        for (int nt2 = 0; nt2 < 4; nt2++) {
            uint32_t bh[4];
            ldsm4(bh, b_addr(st + BOFF, wc * 64 + nt2 * 16, kb, lane, TPGx));
            float* c00 = C[0][nt2 * 2];     float* c10 = C[1][nt2 * 2];
            float* c01 = C[0][nt2 * 2 + 1]; float* c11 = C[1][nt2 * 2 + 1];
            mma16816h(c00, ah[0], bh[0], bh[1]);
            mma16816h(c10, ah[1], bh[0], bh[1]);
            mma16816h(c01, ah[0], bh[2], bh[3]);
            mma16816h(c11, ah[1], bh[2], bh[3]);
            if (NT == 2) {
                mma16816h(c00, al[0], bh[0], bh[1]);
                mma16816h(c10, al[1], bh[0], bh[1]);
                mma16816h(c01, al[0], bh[2], bh[3]);
                mma16816h(c11, al[1], bh[2], bh[3]);
            }
        }
    }
}

template <int NT, int MODE>   // MODE 0: fp16 out (w/ scale), 1: fp32 out
__device__ __forceinline__ void gemm_body(
    const __half* __restrict__ Ahi, const __half* __restrict__ Alo,
    const __half* __restrict__ B, const float* __restrict__ bias, float oscale,
    __half* __restrict__ Ch, float* __restrict__ Cf)
{
    constexpr int CK   = (NT == 1) ? 64 : 32;
    constexpr int NCH  = (NT == 1) ? 16 : 32;
    constexpr uint32_t STG = (NT == 1) ? G1_STG : G2_STG;

    extern __shared__ __align__(128) char smem[];
    uint32_t sb = smem_u32(smem);
    const int tid = threadIdx.x;
    const int wid = tid >> 5, lane = tid & 31;
    const int wr = wid & 3, wc = wid >> 2;
    const int m0 = blockIdx.x * 128, n0 = blockIdx.y * 128;

    float C[2][8][4];
    #pragma unroll
    for (int a = 0; a < 2; a++)
        #pragma unroll
        for (int b = 0; b < 8; b++)
            #pragma unroll
            for (int c = 0; c < 4; c++) C[a][b][c] = 0.f;

    g_load_chunk<NT>(sb,       Ahi, Alo, B, m0, n0, 0,  tid);
    g_load_chunk<NT>(sb + STG, Ahi, Alo, B, m0, n0, CK, tid);

    for (int i = 0; i < NCH; i++) {
        if (i + 1 < NCH) { CP_WAIT1(); } else { CP_WAIT0(); }
        __syncthreads();   // also retires compute of chunk i-1 (stage (i+2)%3)
        if (i + 2 < NCH)
            g_load_chunk<NT>(sb + ((i + 2) % 3) * STG, Ahi, Alo, B,
                             m0, n0, (i + 2) * CK, tid);
        g_compute_chunk<NT>(sb + (i % 3) * STG, lane, wr, wc, C);
    }

    const int gid = lane >> 2, tig = lane & 3;
    #pragma unroll
    for (int mt = 0; mt < 2; mt++) {
        int row0 = m0 + wr * 32 + mt * 16 + gid;
        #pragma unroll
        for (int nt = 0; nt < 8; nt++) {
            int col = n0 + wc * 64 + nt * 8 + tig * 2;
            float b0 = bias[col], b1 = bias[col + 1];
            float v00 = (C[mt][nt][0] + b0) * oscale, v01 = (C[mt][nt][1] + b1) * oscale;
            float v10 = (C[mt][nt][2] + b0) * oscale, v11 = (C[mt][nt][3] + b1) * oscale;
            if (MODE == 0) {
                *(uint32_t*)&Ch[(size_t)row0 * DMODEL + col] = h2u(__floats2half2_rn(v00, v01));
                *(uint32_t*)&Ch[(size_t)(row0 + 8) * DMODEL + col] = h2u(__floats2half2_rn(v10, v11));
            } else {
                *(float2*)&Cf[(size_t)row0 * DMODEL + col] = make_float2(v00, v01);
                *(float2*)&Cf[(size_t)(row0 + 8) * DMODEL + col] = make_float2(v10, v11);
            }
        }
    }
}

__global__ __launch_bounds__(256, 2)
void proj_gemm_kernel(const float* __restrict__ bq, const float* __restrict__ bk,
                      const float* __restrict__ bv)
{
    int z = blockIdx.z;
    const float* bias = (z == 0) ? bq : (z == 1) ? bk : bv;
    float oscale = (z == 0) ? 0.18033688011112042f : 1.0f;  // fold 0.125*log2(e) into q
    if (z == 2)
        gemm_body<2, 0>(g_Xhi[2], g_Xlo[2], g_Wh[2], bias, oscale, g_P[2], nullptr);
    else
        gemm_body<1, 0>(g_Xhi[z], nullptr, g_Wh[z], bias, oscale, g_P[z], nullptr);
}

__global__ __launch_bounds__(256, 2)
void out_gemm_kernel(const float* __restrict__ bo, float* __restrict__ out)
{
    gemm_body<2, 1>(g_Ohi, g_Olo, g_Wh[3], bo, 1.0f, nullptr, out);
}

// ---------------------------------------------------------------------------
// Flash attention, single-term fp16 HMMA (unchanged from round 12).
// ---------------------------------------------------------------------------
#define ATP 144
#define AK_TILE (64 * ATP)       // 9216
#define AQ_TILE (128 * ATP)      // 18432
#define A_KV    AQ_TILE
#define A_STAGE (2 * AK_TILE)    // 18432
#define A_SMEM  (AQ_TILE + 2 * A_STAGE)   // 55296

__device__ __forceinline__ void attn_load_kv(
    uint32_t st, const __half* __restrict__ kk, const __half* __restrict__ vv,
    int j0, int colBase, int tid)
{
    #pragma unroll
    for (int i = 0; i < 4; i++) {
        int idx = tid + i * 256;          // 0..1023
        int mat = idx >> 9;               // 0=K, 1=V
        int j = idx & 511;
        int r = j >> 3, c = j & 7;
        uint32_t so = (uint32_t)r * ATP + c * 16;
        CP16(st + mat * AK_TILE + so,
             (mat ? vv : kk) + (size_t)(j0 + r) * DMODEL + colBase + c * 8);
    }
    CP_COMMIT();
}

__global__ __launch_bounds__(256, 2)
void attn_kernel()
{
    extern __shared__ __align__(128) char smem[];
    uint32_t sb = smem_u32(smem);
    const int tid = threadIdx.x;
    const int wid = tid >> 5, lane = tid & 31;
    const int gid = lane >> 2, tig = lane & 3;
    const int qt = blockIdx.x, h = blockIdx.y;
    const int r0 = qt * 128;
    const int colBase = h * HDK;

    const __half* qp = g_P[0];
    const __half* kp = g_P[1];
    const __half* vp = g_P[2];

    // Q tile (single fp16)
    #pragma unroll
    for (int i = 0; i < 4; i++) {
        int idx = tid + i * 256;
        int r = idx >> 3, c = idx & 7;
        uint32_t so = (uint32_t)r * ATP + c * 16;
        CP16(sb + so, qp + (size_t)(r0 + r) * DMODEL + colBase + c * 8);
    }
    CP_COMMIT();
    attn_load_kv(sb + A_KV, kp, vp, 0, colBase, tid);
    CP_WAIT1();                          // Q arrived
    __syncthreads();

    uint32_t qf[4][4];
    #pragma unroll
    for (int ks = 0; ks < 4; ks++)
        ldsm4(qf[ks], a_addr(sb, wid * 16, ks * 32, lane, ATP));

    float O[8][4];
    #pragma unroll
    for (int a = 0; a < 8; a++)
        #pragma unroll
        for (int b = 0; b < 4; b++) O[a][b] = 0.f;
    float Csum[4] = {0.f, 0.f, 0.f, 0.f};

    for (int jt = 0; jt < 32; jt++) {
        CP_WAIT0();
        __syncthreads();
        if (jt + 1 < 32)
            attn_load_kv(sb + A_KV + ((jt + 1) & 1) * A_STAGE,
                         kp, vp, (jt + 1) * 64, colBase, tid);
        uint32_t stCur = sb + A_KV + (jt & 1) * A_STAGE;

        // ---- scores (1-term) ----
        float sc[8][4];
        #pragma unroll
        for (int a = 0; a < 8; a++)
            #pragma unroll
            for (int b = 0; b < 4; b++) sc[a][b] = 0.f;

        #pragma unroll
        for (int ks = 0; ks < 4; ks++) {
            int kb = ks * 32;
            #pragma unroll
            for (int nt2 = 0; nt2 < 4; nt2++) {
                uint32_t bh[4];
                ldsm4(bh, b_addr(stCur, nt2 * 16, kb, lane, ATP));
                mma16816h(sc[nt2 * 2],     qf[ks], bh[0], bh[1]);
                mma16816h(sc[nt2 * 2 + 1], qf[ks], bh[2], bh[3]);
            }
        }

        // ---- P = exp2(sc), fp32 MUFU precision, packed to fp16 ----
        uint32_t p01[8], p23[8];
        #pragma unroll
        for (int nt = 0; nt < 8; nt++) {
            p01[nt] = h2u(__floats2half2_rn(exp2f(sc[nt][0]), exp2f(sc[nt][1])));
            p23[nt] = h2u(__floats2half2_rn(exp2f(sc[nt][2]), exp2f(sc[nt][3])));
        }

        // ---- PV (1-term) + row-sum via ones-MMA ----
        #pragma unroll
        for (int kt = 0; kt < 4; kt++) {
            uint32_t p[4] = {p01[2 * kt], p23[2 * kt], p01[2 * kt + 1], p23[2 * kt + 1]};
            mma16816h(Csum, p, ONESH2, ONESH2);
            #pragma unroll
            for (int nt2 = 0; nt2 < 4; nt2++) {
                uint32_t vh[4];
                ldsm4t(vh, v_addr(stCur + AK_TILE, kt * 16, nt2 * 32, lane, ATP));
                mma16816h(O[nt2 * 2],     p, vh[0], vh[1]);
                mma16816h(O[nt2 * 2 + 1], p, vh[2], vh[3]);
            }
        }
    }

    float inv0 = 1.f / Csum[0], inv1 = 1.f / Csum[2];
    int rowA = r0 + wid * 16 + gid;
    #pragma unroll
    for (int nt = 0; nt < 8; nt++) {
        int col = colBase + nt * 8 + tig * 2;
        uint32_t ph, pl;
        hilo_packh(O[nt][0] * inv0, O[nt][1] * inv0, ph, pl);
        *(uint32_t*)&g_Ohi[(size_t)rowA * DMODEL + col] = ph;
        *(uint32_t*)&g_Olo[(size_t)rowA * DMODEL + col] = pl;
        hilo_packh(O[nt][2] * inv1, O[nt][3] * inv1, ph, pl);
        *(uint32_t*)&g_Ohi[(size_t)(rowA + 8) * DMODEL + col] = ph;
        *(uint32_t*)&g_Olo[(size_t)(rowA + 8) * DMODEL + col] = pl;
    }
}

// ---------------------------------------------------------------------------
extern "C" void kernel_launch(void* const* d_in, const int* in_sizes, int n_in,
                              void* d_out, int out_size)
{
    const float* Q  = (const float*)d_in[0];
    const float* K  = (const float*)d_in[1];
    const float* V  = (const float*)d_in[2];
    const float* Wq = (const float*)d_in[3];
    const float* bq = (const float*)d_in[4];
    const float* Wk = (const float*)d_in[5];
    const float* bk = (const float*)d_in[6];
    const float* Wv = (const float*)d_in[7];
    const float* bv = (const float*)d_in[8];
    const float* Wo = (const float*)d_in[9];
    const float* bo = (const float*)d_in[10];
    float* out = (float*)d_out;

    cudaFuncSetAttribute(proj_gemm_kernel, cudaFuncAttributeMaxDynamicSharedMemorySize, G_SMEM1);
    cudaFuncSetAttribute(out_gemm_kernel,  cudaFuncAttributeMaxDynamicSharedMemorySize, G_SMEM2);
    cudaFuncSetAttribute(attn_kernel,      cudaFuncAttributeMaxDynamicSharedMemorySize, A_SMEM);

    conv_in_kernel<<<dim3(SEQ * DMODEL / 2048, 3), 256>>>(Q, K, V);
    conv_w3_kernel<<<dim3(16, 1, 48), 256>>>(Wq, Wk, Wv);
    conv_wo_kernel<<<dim3(16, 16, 1), 256>>>(Wo);

    proj_gemm_kernel<<<dim3(16, 8, 3), 256, G_SMEM1>>>(bq, bk, bv);
    attn_kernel<<<dim3(SEQ / 128, NH), 256, A_SMEM>>>();
    out_gemm_kernel<<<dim3(16, 8), 256, G_SMEM2>>>(bo, out);
}

// round 15
// speedup vs baseline: 1.0366x; 1.0366x over previous
#include <cuda_runtime.h>
#include <cuda_fp16.h>
#include <math.h>
#include <stdint.h>

#define SEQ 2048
#define DMODEL 1024
#define NH 16
#define HDK 64

// ---------------------------------------------------------------------------
// Scratch (__device__ globals).
// ---------------------------------------------------------------------------
__device__ __half g_Xhi[3][SEQ * DMODEL];    // inputs Q,K,V (hi)
__device__ __half g_Xlo[3][SEQ * DMODEL];    // inputs lo (used by V-proj only)
__device__ __half g_Wh[4][DMODEL * DMODEL];  // Wq,Wk,Wv,Wo as [N][K], single fp16
__device__ __half g_P[3][SEQ * DMODEL];      // projected q,k,v (q pre-scaled), fp16
__device__ __half g_Ohi[SEQ * DMODEL];       // concat hi
__device__ __half g_Olo[SEQ * DMODEL];       // concat lo

#define ONESH2 0x3C003C00u   // {1.0h, 1.0h}

// ---------------------------------------------------------------------------
// Helpers
// ---------------------------------------------------------------------------
__device__ __forceinline__ uint32_t smem_u32(const void* p) {
    uint32_t a;
    asm("{ .reg .u64 t; cvta.to.shared.u64 t, %1; cvt.u32.u64 %0, t; }" : "=r"(a) : "l"(p));
    return a;
}

#define CP16(dst, src) \
    asm volatile("cp.async.cg.shared.global [%0], [%1], 16;" :: "r"((uint32_t)(dst)), "l"(src) : "memory")
#define CP_COMMIT() asm volatile("cp.async.commit_group;" ::: "memory")
#define CP_WAIT0()  asm volatile("cp.async.wait_group 0;" ::: "memory")
#define CP_WAIT1()  asm volatile("cp.async.wait_group 1;" ::: "memory")

__device__ __forceinline__ void ldsm4(uint32_t* r, uint32_t addr) {
    asm volatile("ldmatrix.sync.aligned.m8n8.x4.shared.b16 {%0,%1,%2,%3}, [%4];"
                 : "=r"(r[0]), "=r"(r[1]), "=r"(r[2]), "=r"(r[3]) : "r"(addr));
}
__device__ __forceinline__ void ldsm4t(uint32_t* r, uint32_t addr) {
    asm volatile("ldmatrix.sync.aligned.m8n8.x4.trans.shared.b16 {%0,%1,%2,%3}, [%4];"
                 : "=r"(r[0]), "=r"(r[1]), "=r"(r[2]), "=r"(r[3]) : "r"(addr));
}
__device__ __forceinline__ void mma16816h(float* c, const uint32_t* a, uint32_t b0, uint32_t b1) {
    asm volatile("mma.sync.aligned.m16n8k16.row.col.f32.f16.f16.f32 "
                 "{%0,%1,%2,%3}, {%4,%5,%6,%7}, {%8,%9}, {%0,%1,%2,%3};"
                 : "+f"(c[0]), "+f"(c[1]), "+f"(c[2]), "+f"(c[3])
                 : "r"(a[0]), "r"(a[1]), "r"(a[2]), "r"(a[3]), "r"(b0), "r"(b1));
}

__device__ __forceinline__ uint32_t h2u(__half2 h) { return *reinterpret_cast<uint32_t*>(&h); }
__device__ __forceinline__ void hilo_packh(float x, float y, uint32_t& ph, uint32_t& pl) {
    __half2 h = __floats2half2_rn(x, y);
    ph = h2u(h);
    float lx = x - __low2float(h);
    float ly = y - __high2float(h);
    pl = h2u(__floats2half2_rn(lx, ly));
}

// ldmatrix address generators, parametric row pitch P (bytes).
__device__ __forceinline__ uint32_t a_addr(uint32_t tb, int r0, int kb, int lane, int P) {
    int sub = lane >> 3, ll = lane & 7;
    return tb + (uint32_t)(r0 + ((sub & 1) << 3) + ll) * P + kb + ((sub >> 1) << 4);
}
__device__ __forceinline__ uint32_t b_addr(uint32_t tb, int n0, int kb, int lane, int P) {
    int sub = lane >> 3, ll = lane & 7;
    return tb + (uint32_t)(n0 + ((sub >> 1) << 3) + ll) * P + kb + ((sub & 1) << 4);
}
__device__ __forceinline__ uint32_t v_addr(uint32_t tb, int k0, int nb, int lane, int P) {
    int sub = lane >> 3, ll = lane & 7;
    return tb + (uint32_t)(k0 + ((sub & 1) << 3) + ll) * P + nb + ((sub >> 1) << 4);
}

// ---------------------------------------------------------------------------
// Conversion kernels
// ---------------------------------------------------------------------------
__global__ void conv_in_kernel(const float* __restrict__ Q, const float* __restrict__ K,
                               const float* __restrict__ V)
{
    int z = blockIdx.y;
    const float* src = (z == 0) ? Q : (z == 1) ? K : V;
    #pragma unroll
    for (int k = 0; k < 2; k++) {
        size_t i = ((size_t)blockIdx.x * 256 + threadIdx.x) * 4 + (size_t)k * (SEQ * DMODEL / 2);
        float4 v = *(const float4*)(src + i);
        uint32_t ph, pl;
        hilo_packh(v.x, v.y, ph, pl);
        *(uint32_t*)&g_Xhi[z][i] = ph; *(uint32_t*)&g_Xlo[z][i] = pl;
        hilo_packh(v.z, v.w, ph, pl);
        *(uint32_t*)&g_Xhi[z][i + 2] = ph; *(uint32_t*)&g_Xlo[z][i + 2] = pl;
    }
}

// Transpose + convert to single fp16: src [R][C] fp32 -> dst [C][R]
__device__ __forceinline__ void conv_w_body(const float* __restrict__ src,
                                            __half* __restrict__ dst,
                                            int R, int C, int bx, int by)
{
    __shared__ float t[64][65];
    int r0 = bx * 64, c0 = by * 64;
    int tid = threadIdx.x;
    #pragma unroll
    for (int i = 0; i < 16; i++) {
        int idx = tid + i * 256;
        int rr = idx >> 6, cc = idx & 63;
        t[cc][rr] = src[(size_t)(r0 + rr) * C + c0 + cc];
    }
    __syncthreads();
    #pragma unroll
    for (int i = 0; i < 16; i++) {
        int idx = tid + i * 256;
        int rr = idx >> 6, cc = idx & 63;
        dst[(size_t)(c0 + rr) * R + r0 + cc] = __float2half_rn(t[rr][cc]);
    }
}

__global__ void conv_w3_kernel(const float* __restrict__ Wq, const float* __restrict__ Wk,
                               const float* __restrict__ Wv)
{
    int which = blockIdx.z >> 4, zz = blockIdx.z & 15;
    const float* src = (which == 0) ? Wq : (which == 1) ? Wk : Wv;
    conv_w_body(src + (size_t)zz * DMODEL * HDK,
                &g_Wh[which][(size_t)zz * DMODEL * HDK], 1024, 64, blockIdx.x, 0);
}

__global__ void conv_wo_kernel(const float* __restrict__ Wo)
{
    conv_w_body(Wo, g_Wh[3], 1024, 1024, blockIdx.x, blockIdx.y);
}

// ---------------------------------------------------------------------------
// HMMA GEMM (round-12 measured-best config, frozen):
// C = A[S][1024] * B^T ([N][K]) + bias. NT=1: A_hi x B. NT=2: (A_hi+A_lo) x B.
// CTA 128x128, 8 warps (warp m32xn64), K-chunk 32, 2-stage cp.async, TPG=80.
// ---------------------------------------------------------------------------
#define TPG 80
#define G_MAT   (128 * TPG)    // 10240
#define G_STAGE (3 * G_MAT)    // 30720 (A_hi, A_lo, B slots; A_lo unused for NT1)
#define G_SMEM  (2 * G_STAGE)  // 61440
#define G_NCHUNK 32

template <int NT>
__device__ __forceinline__ void g_load_chunk(
    uint32_t st, const __half* __restrict__ Ahi, const __half* __restrict__ Alo,
    const __half* __restrict__ B, int m0, int n0, int k0, int tid)
{
    #pragma unroll
    for (int i = 0; i < 2; i++) {
        int j = tid + i * 256;
        int r = j >> 2, c = j & 3;
        CP16(st + (uint32_t)r * TPG + c * 16, Ahi + (size_t)(m0 + r) * DMODEL + k0 + c * 8);
    }
    if (NT == 2) {
        #pragma unroll
        for (int i = 0; i < 2; i++) {
            int j = tid + i * 256;
            int r = j >> 2, c = j & 3;
            CP16(st + G_MAT + (uint32_t)r * TPG + c * 16, Alo + (size_t)(m0 + r) * DMODEL + k0 + c * 8);
        }
    }
    #pragma unroll
    for (int i = 0; i < 2; i++) {
        int j = tid + i * 256;
        int r = j >> 2, c = j & 3;
        CP16(st + 2 * G_MAT + (uint32_t)r * TPG + c * 16, B + (size_t)(n0 + r) * DMODEL + k0 + c * 8);
    }
    CP_COMMIT();
}

template <int NT>
__device__ __forceinline__ void g_compute_chunk(uint32_t st, int lane, int wr, int wc,
                                                float C[2][8][4])
{
    #pragma unroll
    for (int ks = 0; ks < 2; ks++) {
        int kb = ks * 32;
        uint32_t ah[2][4], al[2][4];
        ldsm4(ah[0], a_addr(st, wr * 32,      kb, lane, TPG));
        ldsm4(ah[1], a_addr(st, wr * 32 + 16, kb, lane, TPG));
        if (NT == 2) {
            ldsm4(al[0], a_addr(st + G_MAT, wr * 32,      kb, lane, TPG));
            ldsm4(al[1], a_addr(st + G_MAT, wr * 32 + 16, kb, lane, TPG));
        }
        #pragma unroll
        for (int nt2 = 0; nt2 < 4; nt2++) {
            uint32_t bh[4];
            ldsm4(bh, b_addr(st + 2 * G_MAT, wc * 64 + nt2 * 16, kb, lane, TPG));
            float* c00 = C[0][nt2 * 2];     float* c10 = C[1][nt2 * 2];
            float* c01 = C[0][nt2 * 2 + 1]; float* c11 = C[1][nt2 * 2 + 1];
            mma16816h(c00, ah[0], bh[0], bh[1]);
            mma16816h(c10, ah[1], bh[0], bh[1]);
            mma16816h(c01, ah[0], bh[2], bh[3]);
            mma16816h(c11, ah[1], bh[2], bh[3]);
            if (NT == 2) {
                mma16816h(c00, al[0], bh[0], bh[1]);
                mma16816h(c10, al[1], bh[0], bh[1]);
                mma16816h(c01, al[0], bh[2], bh[3]);
                mma16816h(c11, al[1], bh[2], bh[3]);
            }
        }
    }
}

template <int NT, int MODE>   // MODE 0: fp16 single out (w/ scale), 1: fp32 out
__device__ __forceinline__ void gemm_body(
    const __half* __restrict__ Ahi, const __half* __restrict__ Alo,
    const __half* __restrict__ B, const float* __restrict__ bias, float oscale,
    __half* __restrict__ Ch, float* __restrict__ Cf)
{
    extern __shared__ __align__(128) char smem[];
    uint32_t sb = smem_u32(smem);
    const int tid = threadIdx.x;
    const int wid = tid >> 5, lane = tid & 31;
    const int wr = wid & 3, wc = wid >> 2;
    const int m0 = blockIdx.x * 128, n0 = blockIdx.y * 128;

    float C[2][8][4];
    #pragma unroll
    for (int a = 0; a < 2; a++)
        #pragma unroll
        for (int b = 0; b < 8; b++)
            #pragma unroll
            for (int c = 0; c < 4; c++) C[a][b][c] = 0.f;

    g_load_chunk<NT>(sb, Ahi, Alo, B, m0, n0, 0, tid);

    for (int i = 0; i < G_NCHUNK; i++) {
        if (i + 1 < G_NCHUNK) {
            g_load_chunk<NT>(sb + ((i + 1) & 1) * G_STAGE, Ahi, Alo, B,
                             m0, n0, (i + 1) * 32, tid);
            CP_WAIT1();
        } else {
            CP_WAIT0();
        }
        __syncthreads();
        g_compute_chunk<NT>(sb + (i & 1) * G_STAGE, lane, wr, wc, C);
        __syncthreads();
    }

    const int gid = lane >> 2, tig = lane & 3;
    #pragma unroll
    for (int mt = 0; mt < 2; mt++) {
        int row0 = m0 + wr * 32 + mt * 16 + gid;
        #pragma unroll
        for (int nt = 0; nt < 8; nt++) {
            int col = n0 + wc * 64 + nt * 8 + tig * 2;
            float b0 = bias[col], b1 = bias[col + 1];
            float v00 = (C[mt][nt][0] + b0) * oscale, v01 = (C[mt][nt][1] + b1) * oscale;
            float v10 = (C[mt][nt][2] + b0) * oscale, v11 = (C[mt][nt][3] + b1) * oscale;
            if (MODE == 0) {
                *(uint32_t*)&Ch[(size_t)row0 * DMODEL + col] = h2u(__floats2half2_rn(v00, v01));
                *(uint32_t*)&Ch[(size_t)(row0 + 8) * DMODEL + col] = h2u(__floats2half2_rn(v10, v11));
            } else {
                *(float2*)&Cf[(size_t)row0 * DMODEL + col] = make_float2(v00, v01);
                *(float2*)&Cf[(size_t)(row0 + 8) * DMODEL + col] = make_float2(v10, v11);
            }
        }
    }
}

__global__ __launch_bounds__(256, 2)
void proj_gemm_kernel(const float* __restrict__ bq, const float* __restrict__ bk,
                      const float* __restrict__ bv)
{
    int z = blockIdx.z;
    const float* bias = (z == 0) ? bq : (z == 1) ? bk : bv;
    float oscale = (z == 0) ? 0.18033688011112042f : 1.0f;  // fold 0.125*log2(e) into q
    if (z == 2)
        gemm_body<2, 0>(g_Xhi[2], g_Xlo[2], g_Wh[2], bias, oscale, g_P[2], nullptr);
    else
        gemm_body<1, 0>(g_Xhi[z], nullptr, g_Wh[z], bias, oscale, g_P[z], nullptr);
}

__global__ __launch_bounds__(256, 2)
void out_gemm_kernel(const float* __restrict__ bo, float* __restrict__ out)
{
    gemm_body<2, 1>(g_Ohi, g_Olo, g_Wh[3], bo, 1.0f, nullptr, out);
}

// ---------------------------------------------------------------------------
// Flash attention, single-term fp16 HMMA. q pre-scaled by 0.125*log2e.
// P = h2exp2 (f16x2 MUFU: half the MUFU ops of fp32 exp2f).
// Row sums via ones-MMA. CTA = 128 q-rows x 1 head, 8 warps, K/V double-buffered.
// ---------------------------------------------------------------------------
#define ATP 144
#define AK_TILE (64 * ATP)       // 9216
#define AQ_TILE (128 * ATP)      // 18432
#define A_KV    AQ_TILE
#define A_STAGE (2 * AK_TILE)    // 18432
#define A_SMEM  (AQ_TILE + 2 * A_STAGE)   // 55296

__device__ __forceinline__ void attn_load_kv(
    uint32_t st, const __half* __restrict__ kk, const __half* __restrict__ vv,
    int j0, int colBase, int tid)
{
    #pragma unroll
    for (int i = 0; i < 4; i++) {
        int idx = tid + i * 256;          // 0..1023
        int mat = idx >> 9;               // 0=K, 1=V
        int j = idx & 511;
        int r = j >> 3, c = j & 7;
        uint32_t so = (uint32_t)r * ATP + c * 16;
        CP16(st + mat * AK_TILE + so,
             (mat ? vv : kk) + (size_t)(j0 + r) * DMODEL + colBase + c * 8);
    }
    CP_COMMIT();
}

__global__ __launch_bounds__(256, 2)
void attn_kernel()
{
    extern __shared__ __align__(128) char smem[];
    uint32_t sb = smem_u32(smem);
    const int tid = threadIdx.x;
    const int wid = tid >> 5, lane = tid & 31;
    const int gid = lane >> 2, tig = lane & 3;
    const int qt = blockIdx.x, h = blockIdx.y;
    const int r0 = qt * 128;
    const int colBase = h * HDK;

    const __half* qp = g_P[0];
    const __half* kp = g_P[1];
    const __half* vp = g_P[2];

    // Q tile (single fp16)
    #pragma unroll
    for (int i = 0; i < 4; i++) {
        int idx = tid + i * 256;
        int r = idx >> 3, c = idx & 7;
        uint32_t so = (uint32_t)r * ATP + c * 16;
        CP16(sb + so, qp + (size_t)(r0 + r) * DMODEL + colBase + c * 8);
    }
    CP_COMMIT();
    attn_load_kv(sb + A_KV, kp, vp, 0, colBase, tid);
    CP_WAIT1();                          // Q arrived
    __syncthreads();

    uint32_t qf[4][4];
    #pragma unroll
    for (int ks = 0; ks < 4; ks++)
        ldsm4(qf[ks], a_addr(sb, wid * 16, ks * 32, lane, ATP));

    float O[8][4];
    #pragma unroll
    for (int a = 0; a < 8; a++)
        #pragma unroll
        for (int b = 0; b < 4; b++) O[a][b] = 0.f;
    float Csum[4] = {0.f, 0.f, 0.f, 0.f};

    for (int jt = 0; jt < 32; jt++) {
        CP_WAIT0();
        __syncthreads();
        if (jt + 1 < 32)
            attn_load_kv(sb + A_KV + ((jt + 1) & 1) * A_STAGE,
                         kp, vp, (jt + 1) * 64, colBase, tid);
        uint32_t stCur = sb + A_KV + (jt & 1) * A_STAGE;

        // ---- scores (1-term) ----
        float sc[8][4];
        #pragma unroll
        for (int a = 0; a < 8; a++)
            #pragma unroll
            for (int b = 0; b < 4; b++) sc[a][b] = 0.f;

        #pragma unroll
        for (int ks = 0; ks < 4; ks++) {
            int kb = ks * 32;
            #pragma unroll
            for (int nt2 = 0; nt2 < 4; nt2++) {
                uint32_t bh[4];
                ldsm4(bh, b_addr(stCur, nt2 * 16, kb, lane, ATP));
                mma16816h(sc[nt2 * 2],     qf[ks], bh[0], bh[1]);
                mma16816h(sc[nt2 * 2 + 1], qf[ks], bh[2], bh[3]);
            }
        }

        // ---- P = h2exp2(sc) in f16x2 (half the MUFU ops of fp32 exp2f) ----
        uint32_t p01[8], p23[8];
        #pragma unroll
        for (int nt = 0; nt < 8; nt++) {
            p01[nt] = h2u(h2exp2(__floats2half2_rn(sc[nt][0], sc[nt][1])));
            p23[nt] = h2u(h2exp2(__floats2half2_rn(sc[nt][2], sc[nt][3])));
        }

        // ---- PV (1-term) + row-sum via ones-MMA ----
        #pragma unroll
        for (int kt = 0; kt < 4; kt++) {
            uint32_t p[4] = {p01[2 * kt], p23[2 * kt], p01[2 * kt + 1], p23[2 * kt + 1]};
            mma16816h(Csum, p, ONESH2, ONESH2);
            #pragma unroll
            for (int nt2 = 0; nt2 < 4; nt2++) {
                uint32_t vh[4];
                ldsm4t(vh, v_addr(stCur + AK_TILE, kt * 16, nt2 * 32, lane, ATP));
                mma16816h(O[nt2 * 2],     p, vh[0], vh[1]);
                mma16816h(O[nt2 * 2 + 1], p, vh[2], vh[3]);
            }
        }
    }

    float inv0 = 1.f / Csum[0], inv1 = 1.f / Csum[2];
    int rowA = r0 + wid * 16 + gid;
    #pragma unroll
    for (int nt = 0; nt < 8; nt++) {
        int col = colBase + nt * 8 + tig * 2;
        uint32_t ph, pl;
        hilo_packh(O[nt][0] * inv0, O[nt][1] * inv0, ph, pl);
        *(uint32_t*)&g_Ohi[(size_t)rowA * DMODEL + col] = ph;
        *(uint32_t*)&g_Olo[(size_t)rowA * DMODEL + col] = pl;
        hilo_packh(O[nt][2] * inv1, O[nt][3] * inv1, ph, pl);
        *(uint32_t*)&g_Ohi[(size_t)(rowA + 8) * DMODEL + col] = ph;
        *(uint32_t*)&g_Olo[(size_t)(rowA + 8) * DMODEL + col] = pl;
    }
}

// ---------------------------------------------------------------------------
extern "C" void kernel_launch(void* const* d_in, const int* in_sizes, int n_in,
                              void* d_out, int out_size)
{
    const float* Q  = (const float*)d_in[0];
    const float* K  = (const float*)d_in[1];
    const float* V  = (const float*)d_in[2];
    const float* Wq = (const float*)d_in[3];
    const float* bq = (const float*)d_in[4];
    const float* Wk = (const float*)d_in[5];
    const float* bk = (const float*)d_in[6];
    const float* Wv = (const float*)d_in[7];
    const float* bv = (const float*)d_in[8];
    const float* Wo = (const float*)d_in[9];
    const float* bo = (const float*)d_in[10];
    float* out = (float*)d_out;

    cudaFuncSetAttribute(proj_gemm_kernel, cudaFuncAttributeMaxDynamicSharedMemorySize, G_SMEM);
    cudaFuncSetAttribute(out_gemm_kernel,  cudaFuncAttributeMaxDynamicSharedMemorySize, G_SMEM);
    cudaFuncSetAttribute(attn_kernel,      cudaFuncAttributeMaxDynamicSharedMemorySize, A_SMEM);

    conv_in_kernel<<<dim3(SEQ * DMODEL / 2048, 3), 256>>>(Q, K, V);
    conv_w3_kernel<<<dim3(16, 1, 48), 256>>>(Wq, Wk, Wv);
    conv_wo_kernel<<<dim3(16, 16, 1), 256>>>(Wo);

    proj_gemm_kernel<<<dim3(16, 8, 3), 256, G_SMEM>>>(bq, bk, bv);
    attn_kernel<<<dim3(SEQ / 128, NH), 256, A_SMEM>>>();
    out_gemm_kernel<<<dim3(16, 8), 256, G_SMEM>>>(bo, out);
}

// round 16
// speedup vs baseline: 1.1988x; 1.1565x over previous
#include <cuda_runtime.h>
#include <cuda_fp16.h>
#include <math.h>
#include <stdint.h>

#define SEQ 2048
#define DMODEL 1024
#define NH 16
#define HDK 64

// ---------------------------------------------------------------------------
// Scratch (__device__ globals).
// ---------------------------------------------------------------------------
__device__ __half g_Xhi[3][SEQ * DMODEL];    // inputs Q,K,V (fp16)
__device__ __half g_Wh[4][DMODEL * DMODEL];  // Wq,Wk,Wv,Wo as [N][K], single fp16
__device__ __half g_P[3][SEQ * DMODEL];      // projected q,k,v (q pre-scaled), fp16
__device__ __half g_Ohi[SEQ * DMODEL];       // concat hi
__device__ __half g_Olo[SEQ * DMODEL];       // concat lo

#define ONESH2 0x3C003C00u   // {1.0h, 1.0h}

// ---------------------------------------------------------------------------
// Helpers
// ---------------------------------------------------------------------------
__device__ __forceinline__ uint32_t smem_u32(const void* p) {
    uint32_t a;
    asm("{ .reg .u64 t; cvta.to.shared.u64 t, %1; cvt.u32.u64 %0, t; }" : "=r"(a) : "l"(p));
    return a;
}

#define CP16(dst, src) \
    asm volatile("cp.async.cg.shared.global [%0], [%1], 16;" :: "r"((uint32_t)(dst)), "l"(src) : "memory")
#define CP_COMMIT() asm volatile("cp.async.commit_group;" ::: "memory")
#define CP_WAIT0()  asm volatile("cp.async.wait_group 0;" ::: "memory")
#define CP_WAIT1()  asm volatile("cp.async.wait_group 1;" ::: "memory")

__device__ __forceinline__ void ldsm4(uint32_t* r, uint32_t addr) {
    asm volatile("ldmatrix.sync.aligned.m8n8.x4.shared.b16 {%0,%1,%2,%3}, [%4];"
                 : "=r"(r[0]), "=r"(r[1]), "=r"(r[2]), "=r"(r[3]) : "r"(addr));
}
__device__ __forceinline__ void ldsm4t(uint32_t* r, uint32_t addr) {
    asm volatile("ldmatrix.sync.aligned.m8n8.x4.trans.shared.b16 {%0,%1,%2,%3}, [%4];"
                 : "=r"(r[0]), "=r"(r[1]), "=r"(r[2]), "=r"(r[3]) : "r"(addr));
}
__device__ __forceinline__ void mma16816h(float* c, const uint32_t* a, uint32_t b0, uint32_t b1) {
    asm volatile("mma.sync.aligned.m16n8k16.row.col.f32.f16.f16.f32 "
                 "{%0,%1,%2,%3}, {%4,%5,%6,%7}, {%8,%9}, {%0,%1,%2,%3};"
                 : "+f"(c[0]), "+f"(c[1]), "+f"(c[2]), "+f"(c[3])
                 : "r"(a[0]), "r"(a[1]), "r"(a[2]), "r"(a[3]), "r"(b0), "r"(b1));
}

__device__ __forceinline__ uint32_t h2u(__half2 h) { return *reinterpret_cast<uint32_t*>(&h); }
__device__ __forceinline__ void hilo_packh(float x, float y, uint32_t& ph, uint32_t& pl) {
    __half2 h = __floats2half2_rn(x, y);
    ph = h2u(h);
    float lx = x - __low2float(h);
    float ly = y - __high2float(h);
    pl = h2u(__floats2half2_rn(lx, ly));
}

// ldmatrix address generators, parametric row pitch P (bytes).
__device__ __forceinline__ uint32_t a_addr(uint32_t tb, int r0, int kb, int lane, int P) {
    int sub = lane >> 3, ll = lane & 7;
    return tb + (uint32_t)(r0 + ((sub & 1) << 3) + ll) * P + kb + ((sub >> 1) << 4);
}
__device__ __forceinline__ uint32_t b_addr(uint32_t tb, int n0, int kb, int lane, int P) {
    int sub = lane >> 3, ll = lane & 7;
    return tb + (uint32_t)(n0 + ((sub >> 1) << 3) + ll) * P + kb + ((sub & 1) << 4);
}
__device__ __forceinline__ uint32_t v_addr(uint32_t tb, int k0, int nb, int lane, int P) {
    int sub = lane >> 3, ll = lane & 7;
    return tb + (uint32_t)(k0 + ((sub & 1) << 3) + ll) * P + nb + ((sub >> 1) << 4);
}

// ---------------------------------------------------------------------------
// Merged conversion kernel: one launch covers
//   blocks [0, 3072): inputs Q,K,V fp32 -> fp16 (hi only; z = bx/1024)
//   blocks [3072, 3840): Wq,Wk,Wv transpose+convert
//   blocks [3840, 4096): Wo transpose+convert
// ---------------------------------------------------------------------------
__device__ __forceinline__ void conv_w_body(const float* __restrict__ src,
                                            __half* __restrict__ dst,
                                            int R, int C, int bx, int by)
{
    __shared__ float t[64][65];
    int r0 = bx * 64, c0 = by * 64;
    int tid = threadIdx.x;
    #pragma unroll
    for (int i = 0; i < 16; i++) {
        int idx = tid + i * 256;
        int rr = idx >> 6, cc = idx & 63;
        t[cc][rr] = src[(size_t)(r0 + rr) * C + c0 + cc];
    }
    __syncthreads();
    #pragma unroll
    for (int i = 0; i < 16; i++) {
        int idx = tid + i * 256;
        int rr = idx >> 6, cc = idx & 63;
        dst[(size_t)(c0 + rr) * R + r0 + cc] = __float2half_rn(t[rr][cc]);
    }
}

__global__ void conv_all_kernel(const float* __restrict__ Q, const float* __restrict__ K,
                                const float* __restrict__ V,
                                const float* __restrict__ Wq, const float* __restrict__ Wk,
                                const float* __restrict__ Wv, const float* __restrict__ Wo)
{
    int bx = blockIdx.x;
    if (bx < 3072) {
        int z = bx / 1024, xx = bx % 1024;
        const float* src = (z == 0) ? Q : (z == 1) ? K : V;
        #pragma unroll
        for (int k = 0; k < 2; k++) {
            size_t i = ((size_t)xx * 256 + threadIdx.x) * 4 + (size_t)k * (SEQ * DMODEL / 2);
            float4 v = *(const float4*)(src + i);
            *(uint32_t*)&g_Xhi[z][i]     = h2u(__floats2half2_rn(v.x, v.y));
            *(uint32_t*)&g_Xhi[z][i + 2] = h2u(__floats2half2_rn(v.z, v.w));
        }
    } else if (bx < 3840) {
        int t = bx - 3072;
        int which = t / 256, rem = t % 256;
        int zz = rem / 16, bxx = rem % 16;
        const float* src = (which == 0) ? Wq : (which == 1) ? Wk : Wv;
        conv_w_body(src + (size_t)zz * DMODEL * HDK,
                    &g_Wh[which][(size_t)zz * DMODEL * HDK], 1024, 64, bxx, 0);
    } else {
        int t = bx - 3840;
        conv_w_body(Wo, g_Wh[3], 1024, 1024, t / 16, t % 16);
    }
}

// ---------------------------------------------------------------------------
// HMMA GEMM (round-12 measured-best config, frozen):
// C = A[S][1024] * B^T ([N][K]) + bias. NT=1: A_hi x B. NT=2: (A_hi+A_lo) x B.
// CTA 128x128, 8 warps (warp m32xn64), K-chunk 32, 2-stage cp.async, TPG=80.
// ---------------------------------------------------------------------------
#define TPG 80
#define G_MAT   (128 * TPG)    // 10240
#define G_STAGE (3 * G_MAT)    // 30720 (A_hi, A_lo, B slots; A_lo unused for NT1)
#define G_SMEM  (2 * G_STAGE)  // 61440
#define G_NCHUNK 32

template <int NT>
__device__ __forceinline__ void g_load_chunk(
    uint32_t st, const __half* __restrict__ Ahi, const __half* __restrict__ Alo,
    const __half* __restrict__ B, int m0, int n0, int k0, int tid)
{
    #pragma unroll
    for (int i = 0; i < 2; i++) {
        int j = tid + i * 256;
        int r = j >> 2, c = j & 3;
        CP16(st + (uint32_t)r * TPG + c * 16, Ahi + (size_t)(m0 + r) * DMODEL + k0 + c * 8);
    }
    if (NT == 2) {
        #pragma unroll
        for (int i = 0; i < 2; i++) {
            int j = tid + i * 256;
            int r = j >> 2, c = j & 3;
            CP16(st + G_MAT + (uint32_t)r * TPG + c * 16, Alo + (size_t)(m0 + r) * DMODEL + k0 + c * 8);
        }
    }
    #pragma unroll
    for (int i = 0; i < 2; i++) {
        int j = tid + i * 256;
        int r = j >> 2, c = j & 3;
        CP16(st + 2 * G_MAT + (uint32_t)r * TPG + c * 16, B + (size_t)(n0 + r) * DMODEL + k0 + c * 8);
    }
    CP_COMMIT();
}

template <int NT>
__device__ __forceinline__ void g_compute_chunk(uint32_t st, int lane, int wr, int wc,
                                                float C[2][8][4])
{
    #pragma unroll
    for (int ks = 0; ks < 2; ks++) {
        int kb = ks * 32;
        uint32_t ah[2][4], al[2][4];
        ldsm4(ah[0], a_addr(st, wr * 32,      kb, lane, TPG));
        ldsm4(ah[1], a_addr(st, wr * 32 + 16, kb, lane, TPG));
        if (NT == 2) {
            ldsm4(al[0], a_addr(st + G_MAT, wr * 32,      kb, lane, TPG));
            ldsm4(al[1], a_addr(st + G_MAT, wr * 32 + 16, kb, lane, TPG));
        }
        #pragma unroll
        for (int nt2 = 0; nt2 < 4; nt2++) {
            uint32_t bh[4];
            ldsm4(bh, b_addr(st + 2 * G_MAT, wc * 64 + nt2 * 16, kb, lane, TPG));
            float* c00 = C[0][nt2 * 2];     float* c10 = C[1][nt2 * 2];
            float* c01 = C[0][nt2 * 2 + 1]; float* c11 = C[1][nt2 * 2 + 1];
            mma16816h(c00, ah[0], bh[0], bh[1]);
            mma16816h(c10, ah[1], bh[0], bh[1]);
            mma16816h(c01, ah[0], bh[2], bh[3]);
            mma16816h(c11, ah[1], bh[2], bh[3]);
            if (NT == 2) {
                mma16816h(c00, al[0], bh[0], bh[1]);
                mma16816h(c10, al[1], bh[0], bh[1]);
                mma16816h(c01, al[0], bh[2], bh[3]);
                mma16816h(c11, al[1], bh[2], bh[3]);
            }
        }
    }
}

template <int NT, int MODE>   // MODE 0: fp16 single out (w/ scale), 1: fp32 out
__device__ __forceinline__ void gemm_body(
    const __half* __restrict__ Ahi, const __half* __restrict__ Alo,
    const __half* __restrict__ B, const float* __restrict__ bias, float oscale,
    __half* __restrict__ Ch, float* __restrict__ Cf)
{
    extern __shared__ __align__(128) char smem[];
    uint32_t sb = smem_u32(smem);
    const int tid = threadIdx.x;
    const int wid = tid >> 5, lane = tid & 31;
    const int wr = wid & 3, wc = wid >> 2;
    const int m0 = blockIdx.x * 128, n0 = blockIdx.y * 128;

    float C[2][8][4];
    #pragma unroll
    for (int a = 0; a < 2; a++)
        #pragma unroll
        for (int b = 0; b < 8; b++)
            #pragma unroll
            for (int c = 0; c < 4; c++) C[a][b][c] = 0.f;

    g_load_chunk<NT>(sb, Ahi, Alo, B, m0, n0, 0, tid);

    for (int i = 0; i < G_NCHUNK; i++) {
        if (i + 1 < G_NCHUNK) {
            g_load_chunk<NT>(sb + ((i + 1) & 1) * G_STAGE, Ahi, Alo, B,
                             m0, n0, (i + 1) * 32, tid);
            CP_WAIT1();
        } else {
            CP_WAIT0();
        }
        __syncthreads();
        g_compute_chunk<NT>(sb + (i & 1) * G_STAGE, lane, wr, wc, C);
        __syncthreads();
    }

    const int gid = lane >> 2, tig = lane & 3;
    #pragma unroll
    for (int mt = 0; mt < 2; mt++) {
        int row0 = m0 + wr * 32 + mt * 16 + gid;
        #pragma unroll
        for (int nt = 0; nt < 8; nt++) {
            int col = n0 + wc * 64 + nt * 8 + tig * 2;
            float b0 = bias[col], b1 = bias[col + 1];
            float v00 = (C[mt][nt][0] + b0) * oscale, v01 = (C[mt][nt][1] + b1) * oscale;
            float v10 = (C[mt][nt][2] + b0) * oscale, v11 = (C[mt][nt][3] + b1) * oscale;
            if (MODE == 0) {
                *(uint32_t*)&Ch[(size_t)row0 * DMODEL + col] = h2u(__floats2half2_rn(v00, v01));
                *(uint32_t*)&Ch[(size_t)(row0 + 8) * DMODEL + col] = h2u(__floats2half2_rn(v10, v11));
            } else {
                *(float2*)&Cf[(size_t)row0 * DMODEL + col] = make_float2(v00, v01);
                *(float2*)&Cf[(size_t)(row0 + 8) * DMODEL + col] = make_float2(v10, v11);
            }
        }
    }
}

__global__ __launch_bounds__(256, 2)
void proj_gemm_kernel(const float* __restrict__ bq, const float* __restrict__ bk,
                      const float* __restrict__ bv)
{
    int z = blockIdx.z;
    const float* bias = (z == 0) ? bq : (z == 1) ? bk : bv;
    float oscale = (z == 0) ? 0.18033688011112042f : 1.0f;  // fold 0.125*log2(e) into q
    gemm_body<1, 0>(g_Xhi[z], nullptr, g_Wh[z], bias, oscale, g_P[z], nullptr);
}

__global__ __launch_bounds__(256, 2)
void out_gemm_kernel(const float* __restrict__ bo, float* __restrict__ out)
{
    gemm_body<2, 1>(g_Ohi, g_Olo, g_Wh[3], bo, 1.0f, nullptr, out);
}

// ---------------------------------------------------------------------------
// Flash attention, single-term fp16 HMMA (round-12 exact). q pre-scaled.
// P = exp2f (fp32 MUFU) -> fp16. Row sums via ones-MMA.
// CTA = 128 q-rows x 1 head, 8 warps, K/V double-buffered.
// ---------------------------------------------------------------------------
#define ATP 144
#define AK_TILE (64 * ATP)       // 9216
#define AQ_TILE (128 * ATP)      // 18432
#define A_KV    AQ_TILE
#define A_STAGE (2 * AK_TILE)    // 18432
#define A_SMEM  (AQ_TILE + 2 * A_STAGE)   // 55296

__device__ __forceinline__ void attn_load_kv(
    uint32_t st, const __half* __restrict__ kk, const __half* __restrict__ vv,
    int j0, int colBase, int tid)
{
    #pragma unroll
    for (int i = 0; i < 4; i++) {
        int idx = tid + i * 256;          // 0..1023
        int mat = idx >> 9;               // 0=K, 1=V
        int j = idx & 511;
        int r = j >> 3, c = j & 7;
        uint32_t so = (uint32_t)r * ATP + c * 16;
        CP16(st + mat * AK_TILE + so,
             (mat ? vv : kk) + (size_t)(j0 + r) * DMODEL + colBase + c * 8);
    }
    CP_COMMIT();
}

__global__ __launch_bounds__(256, 2)
void attn_kernel()
{
    extern __shared__ __align__(128) char smem[];
    uint32_t sb = smem_u32(smem);
    const int tid = threadIdx.x;
    const int wid = tid >> 5, lane = tid & 31;
    const int gid = lane >> 2, tig = lane & 3;
    const int qt = blockIdx.x, h = blockIdx.y;
    const int r0 = qt * 128;
    const int colBase = h * HDK;

    const __half* qp = g_P[0];
    const __half* kp = g_P[1];
    const __half* vp = g_P[2];

    // Q tile (single fp16)
    #pragma unroll
    for (int i = 0; i < 4; i++) {
        int idx = tid + i * 256;
        int r = idx >> 3, c = idx & 7;
        uint32_t so = (uint32_t)r * ATP + c * 16;
        CP16(sb + so, qp + (size_t)(r0 + r) * DMODEL + colBase + c * 8);
    }
    CP_COMMIT();
    attn_load_kv(sb + A_KV, kp, vp, 0, colBase, tid);
    CP_WAIT1();                          // Q arrived
    __syncthreads();

    uint32_t qf[4][4];
    #pragma unroll
    for (int ks = 0; ks < 4; ks++)
        ldsm4(qf[ks], a_addr(sb, wid * 16, ks * 32, lane, ATP));

    float O[8][4];
    #pragma unroll
    for (int a = 0; a < 8; a++)
        #pragma unroll
        for (int b = 0; b < 4; b++) O[a][b] = 0.f;
    float Csum[4] = {0.f, 0.f, 0.f, 0.f};

    for (int jt = 0; jt < 32; jt++) {
        CP_WAIT0();
        __syncthreads();
        if (jt + 1 < 32)
            attn_load_kv(sb + A_KV + ((jt + 1) & 1) * A_STAGE,
                         kp, vp, (jt + 1) * 64, colBase, tid);
        uint32_t stCur = sb + A_KV + (jt & 1) * A_STAGE;

        // ---- scores (1-term) ----
        float sc[8][4];
        #pragma unroll
        for (int a = 0; a < 8; a++)
            #pragma unroll
            for (int b = 0; b < 4; b++) sc[a][b] = 0.f;

        #pragma unroll
        for (int ks = 0; ks < 4; ks++) {
            int kb = ks * 32;
            #pragma unroll
            for (int nt2 = 0; nt2 < 4; nt2++) {
                uint32_t bh[4];
                ldsm4(bh, b_addr(stCur, nt2 * 16, kb, lane, ATP));
                mma16816h(sc[nt2 * 2],     qf[ks], bh[0], bh[1]);
                mma16816h(sc[nt2 * 2 + 1], qf[ks], bh[2], bh[3]);
            }
        }

        // ---- P = exp2(sc), fp32 MUFU precision, packed to fp16 ----
        uint32_t p01[8], p23[8];
        #pragma unroll
        for (int nt = 0; nt < 8; nt++) {
            p01[nt] = h2u(__floats2half2_rn(exp2f(sc[nt][0]), exp2f(sc[nt][1])));
            p23[nt] = h2u(__floats2half2_rn(exp2f(sc[nt][2]), exp2f(sc[nt][3])));
        }

        // ---- PV (1-term) + row-sum via ones-MMA ----
        #pragma unroll
        for (int kt = 0; kt < 4; kt++) {
            uint32_t p[4] = {p01[2 * kt], p23[2 * kt], p01[2 * kt + 1], p23[2 * kt + 1]};
            mma16816h(Csum, p, ONESH2, ONESH2);
            #pragma unroll
            for (int nt2 = 0; nt2 < 4; nt2++) {
                uint32_t vh[4];
                ldsm4t(vh, v_addr(stCur + AK_TILE, kt * 16, nt2 * 32, lane, ATP));
                mma16816h(O[nt2 * 2],     p, vh[0], vh[1]);
                mma16816h(O[nt2 * 2 + 1], p, vh[2], vh[3]);
            }
        }
    }

    float inv0 = 1.f / Csum[0], inv1 = 1.f / Csum[2];
    int rowA = r0 + wid * 16 + gid;
    #pragma unroll
    for (int nt = 0; nt < 8; nt++) {
        int col = colBase + nt * 8 + tig * 2;
        uint32_t ph, pl;
        hilo_packh(O[nt][0] * inv0, O[nt][1] * inv0, ph, pl);
        *(uint32_t*)&g_Ohi[(size_t)rowA * DMODEL + col] = ph;
        *(uint32_t*)&g_Olo[(size_t)rowA * DMODEL + col] = pl;
        hilo_packh(O[nt][2] * inv1, O[nt][3] * inv1, ph, pl);
        *(uint32_t*)&g_Ohi[(size_t)(rowA + 8) * DMODEL + col] = ph;
        *(uint32_t*)&g_Olo[(size_t)(rowA + 8) * DMODEL + col] = pl;
    }
}

// ---------------------------------------------------------------------------
extern "C" void kernel_launch(void* const* d_in, const int* in_sizes, int n_in,
                              void* d_out, int out_size)
{
    const float* Q  = (const float*)d_in[0];
    const float* K  = (const float*)d_in[1];
    const float* V  = (const float*)d_in[2];
    const float* Wq = (const float*)d_in[3];
    const float* bq = (const float*)d_in[4];
    const float* Wk = (const float*)d_in[5];
    const float* bk = (const float*)d_in[6];
    const float* Wv = (const float*)d_in[7];
    const float* bv = (const float*)d_in[8];
    const float* Wo = (const float*)d_in[9];
    const float* bo = (const float*)d_in[10];
    float* out = (float*)d_out;

    cudaFuncSetAttribute(proj_gemm_kernel, cudaFuncAttributeMaxDynamicSharedMemorySize, G_SMEM);
    cudaFuncSetAttribute(out_gemm_kernel,  cudaFuncAttributeMaxDynamicSharedMemorySize, G_SMEM);
    cudaFuncSetAttribute(attn_kernel,      cudaFuncAttributeMaxDynamicSharedMemorySize, A_SMEM);

    conv_all_kernel<<<4096, 256>>>(Q, K, V, Wq, Wk, Wv, Wo);

    proj_gemm_kernel<<<dim3(16, 8, 3), 256, G_SMEM>>>(bq, bk, bv);
    attn_kernel<<<dim3(SEQ / 128, NH), 256, A_SMEM>>>();
    out_gemm_kernel<<<dim3(16, 8), 256, G_SMEM>>>(bo, out);
}